// round 2
// baseline (speedup 1.0000x reference)
#include <cuda_runtime.h>

// Problem constants (fixed by setup_inputs)
#define BB    64      // batch_size
#define NMAX  768     // max_num_nodes
#define FF    512     // hidden dim
#define HH    16      // num heads
#define NEG_INF_F (-1000000000.0f)

__device__ int g_starts[BB + 1];
__device__ int g_counts[BB];

// Kernel 1: starts[b] = lower_bound(batch_ids, b); counts[b] = starts[b+1]-starts[b].
__global__ void k_starts(const int* __restrict__ batch_ids, int N) {
    int b = threadIdx.x;
    if (b <= BB) {
        int lo = 0, hi = N;
        while (lo < hi) {
            int mid = (lo + hi) >> 1;
            if (batch_ids[mid] < b) lo = mid + 1; else hi = mid;
        }
        g_starts[b] = lo;
    }
    __syncthreads();
    if (b < BB) g_counts[b] = g_starts[b + 1] - g_starts[b];
}

// Kernel 2: dense_x gather + Dmask.
// One block per dense row (B*NMAX rows), 128 threads x float4 = 512 floats.
// batch_ids is sorted, so graph b's nodes are the contiguous slice
// [starts[b], starts[b]+counts[b]) -> pure gather, no atomics.
__global__ void k_dense(const float* __restrict__ x,
                        float* __restrict__ dense,
                        float* __restrict__ dmask) {
    int row = blockIdx.x;
    int b = row / NMAX;
    int i = row - b * NMAX;
    int cnt = g_counts[b];
    bool valid = (i < cnt);
    int t = threadIdx.x;

    float4 v = make_float4(0.f, 0.f, 0.f, 0.f);
    if (valid) {
        const float4* src =
            reinterpret_cast<const float4*>(x + (size_t)(g_starts[b] + i) * FF);
        v = src[t];
    }
    reinterpret_cast<float4*>(dense + (size_t)row * FF)[t] = v;

    if (t == 0) dmask[row] = valid ? 1.0f : 0.0f;
}

// Kernel 3: attn_mask fill. attn[b,h,q,j] = (j < count[b]) ? 0 : -1e9.
// Per-b chunk = H*NMAX*(NMAX/4) = 2,359,296 float4.
// grid = (144, B), 256 threads: per-b stride = 144*256 = 36864 = 192*192,
// a multiple of the row length (192 float4) -> each thread's column index
// (and thus its float4 value) is loop-invariant. 64 pure STG.128 per thread.
__global__ void k_attn(float4* __restrict__ attn) {
    const int b = blockIdx.y;
    const long long per_b = (long long)HH * NMAX * (NMAX / 4); // 2,359,296
    const int idx0 = blockIdx.x * blockDim.x + threadIdx.x;    // [0, 36864)
    const int j4 = idx0 % (NMAX / 4);                          // loop-invariant col
    const int cnt = g_counts[b];
    const int j = j4 * 4;

    float4 v;
    v.x = (j + 0 < cnt) ? 0.0f : NEG_INF_F;
    v.y = (j + 1 < cnt) ? 0.0f : NEG_INF_F;
    v.z = (j + 2 < cnt) ? 0.0f : NEG_INF_F;
    v.w = (j + 3 < cnt) ? 0.0f : NEG_INF_F;

    float4* base = attn + (long long)b * per_b + idx0;
    const int stride = 144 * 256; // 36864
    #pragma unroll 16
    for (int k = 0; k < 64; ++k) {
        base[(long long)k * stride] = v;
    }
}

extern "C" void kernel_launch(void* const* d_in, const int* in_sizes, int n_in,
                              void* d_out, int out_size) {
    const float* x         = (const float*)d_in[0];
    const int*   batch_ids = (const int*)d_in[1];
    int N = in_sizes[1]; // 32768

    float* out   = (float*)d_out;
    float* dense = out;                                  // B*NMAX*F
    float* dmask = dense + (size_t)BB * NMAX * FF;       // B*NMAX
    float* attn  = dmask + (size_t)BB * NMAX;            // B*H*NMAX*NMAX

    k_starts<<<1, 128>>>(batch_ids, N);
    k_dense<<<BB * NMAX, 128>>>(x, dense, dmask);
    k_attn<<<dim3(144, BB), 256>>>((float4*)attn);
}